// round 4
// baseline (speedup 1.0000x reference)
#include <cuda_runtime.h>

#define ICH 32
#define OCH 32
#define HH 512
#define WW 512
#define TW 32
#define TH 16
#define ICCHUNK 16

// ---- packed f32x2 helpers (Blackwell sm_103a) ----
__device__ __forceinline__ unsigned long long pk2(float lo, float hi) {
    unsigned long long r;
    asm("mov.b64 %0, {%1,%2};" : "=l"(r) : "f"(lo), "f"(hi));
    return r;
}
__device__ __forceinline__ void fma2(unsigned long long& d, unsigned long long a, unsigned long long b) {
    asm("fma.rn.f32x2 %0, %1, %2, %0;" : "+l"(d) : "l"(a), "l"(b));
}

// Duplicated weights in global: wdup[((oh*ICH + ic)*9 + r*3 + s)*16 + ocl] = (w,w)
__device__ unsigned long long wdup_g[2 * ICH * 9 * 16];

__global__ void repack_weights(const float* __restrict__ w) {
    int idx = blockIdx.x * blockDim.x + threadIdx.x;
    if (idx >= 2 * ICH * 9 * 16) return;
    int ocl = idx & 15;
    int t   = idx >> 4;
    int rs  = t % 9;
    int ic  = (t / 9) & 31;
    int oh  = t / (9 * ICH);
    int ocg = oh * 16 + ocl;
    float v = w[(ocg * ICH + ic) * 9 + rs];
    wdup_g[idx] = pk2(v, v);
}

// smem: one 16-channel chunk of the input tile: in_s[(icl*18 + row)*36 + col]
#define SMEM_BYTES (ICCHUNK * 18 * 36 * 4)

__global__ void __launch_bounds__(256, 3) conv3x3_kernel(
    const float* __restrict__ x,
    const float* __restrict__ bias,
    float* __restrict__ out)
{
    extern __shared__ float in_s[];

    const int tid   = threadIdx.x;
    const int nz    = blockIdx.z;        // n*2 + ohalf
    const int n     = nz >> 1;
    const int oh    = nz & 1;
    const int row0  = blockIdx.y * TH;
    const int col0  = blockIdx.x * TW;

    // ---- per-thread work assignment: 4 oc x 8 cols (4 pixel pairs) ----
    const int ocg  = tid >> 6;           // 0..3
    const int pg   = tid & 63;
    const int orow = pg >> 2;            // 0..15
    const int cb   = (pg & 3) * 8;       // 0,8,16,24

    unsigned long long acc[4][4];
    #pragma unroll
    for (int i = 0; i < 4; i++) {
        float b = __ldg(&bias[oh * 16 + ocg * 4 + i]);
        unsigned long long bb = pk2(b, b);
        #pragma unroll
        for (int j = 0; j < 4; j++) acc[i][j] = bb;
    }

    const float* xin = x + (size_t)n * ICH * HH * WW;
    const unsigned long long* wbase0 = &wdup_g[((size_t)oh * ICH * 9) * 16 + ocg * 4];

    for (int c = 0; c < ICH / ICCHUNK; c++) {
        // ---- stage this chunk's input tile (with halo, zero padded) ----
        for (int e = tid; e < ICCHUNK * 18 * 34; e += 256) {
            int col = e % 34;
            int t   = e / 34;
            int row = t % 18;
            int icl = t / 18;
            int gy = row0 + row - 1;
            int gx = col0 + col - 1;
            float v = 0.0f;
            if ((unsigned)gy < (unsigned)HH && (unsigned)gx < (unsigned)WW)
                v = xin[(((c * ICCHUNK + icl) * HH + gy)) * WW + gx];
            in_s[(icl * 18 + row) * 36 + col] = v;
        }
        __syncthreads();

        for (int icl = 0; icl < ICCHUNK; icl++) {
            const int ic = c * ICCHUNK + icl;
            #pragma unroll
            for (int r = 0; r < 3; r++) {
                const float* xrow = &in_s[(icl * 18 + orow + r) * 36 + cb];
                float4 xa = *(const float4*)(xrow);
                float4 xb = *(const float4*)(xrow + 4);
                float2 xc = *(const float2*)(xrow + 8);

                unsigned long long p0 = pk2(xa.x, xa.y);
                unsigned long long p1 = pk2(xa.z, xa.w);
                unsigned long long p2 = pk2(xb.x, xb.y);
                unsigned long long p3 = pk2(xb.z, xb.w);
                unsigned long long p4 = pk2(xc.x, xc.y);
                unsigned long long q0 = pk2(xa.y, xa.z);
                unsigned long long q1 = pk2(xa.w, xb.x);
                unsigned long long q2 = pk2(xb.y, xb.z);
                unsigned long long q3 = pk2(xb.w, xc.x);

                const unsigned long long* wr = wbase0 + (size_t)(ic * 9 + r * 3) * 16;
                const ulonglong2* w0 = (const ulonglong2*)(wr);
                const ulonglong2* w1 = (const ulonglong2*)(wr + 16);
                const ulonglong2* w2 = (const ulonglong2*)(wr + 32);

                // s = 0: pairs p0..p3
                #pragma unroll
                for (int i2 = 0; i2 < 2; i2++) {
                    ulonglong2 wv = __ldg(&w0[i2]);
                    fma2(acc[2*i2+0][0], wv.x, p0);
                    fma2(acc[2*i2+0][1], wv.x, p1);
                    fma2(acc[2*i2+0][2], wv.x, p2);
                    fma2(acc[2*i2+0][3], wv.x, p3);
                    fma2(acc[2*i2+1][0], wv.y, p0);
                    fma2(acc[2*i2+1][1], wv.y, p1);
                    fma2(acc[2*i2+1][2], wv.y, p2);
                    fma2(acc[2*i2+1][3], wv.y, p3);
                }
                // s = 1: pairs q0..q3
                #pragma unroll
                for (int i2 = 0; i2 < 2; i2++) {
                    ulonglong2 wv = __ldg(&w1[i2]);
                    fma2(acc[2*i2+0][0], wv.x, q0);
                    fma2(acc[2*i2+0][1], wv.x, q1);
                    fma2(acc[2*i2+0][2], wv.x, q2);
                    fma2(acc[2*i2+0][3], wv.x, q3);
                    fma2(acc[2*i2+1][0], wv.y, q0);
                    fma2(acc[2*i2+1][1], wv.y, q1);
                    fma2(acc[2*i2+1][2], wv.y, q2);
                    fma2(acc[2*i2+1][3], wv.y, q3);
                }
                // s = 2: pairs p1..p4
                #pragma unroll
                for (int i2 = 0; i2 < 2; i2++) {
                    ulonglong2 wv = __ldg(&w2[i2]);
                    fma2(acc[2*i2+0][0], wv.x, p1);
                    fma2(acc[2*i2+0][1], wv.x, p2);
                    fma2(acc[2*i2+0][2], wv.x, p3);
                    fma2(acc[2*i2+0][3], wv.x, p4);
                    fma2(acc[2*i2+1][0], wv.y, p1);
                    fma2(acc[2*i2+1][1], wv.y, p2);
                    fma2(acc[2*i2+1][2], wv.y, p3);
                    fma2(acc[2*i2+1][3], wv.y, p4);
                }
            }
        }
        __syncthreads();
    }

    // ---- store: 4 oc planes, 8 contiguous cols each (2x 16B stores) ----
    const int gy = row0 + orow;
    float* op = out + (((size_t)n * OCH + oh * 16 + ocg * 4) * HH + gy) * WW + col0 + cb;
    #pragma unroll
    for (int i = 0; i < 4; i++) {
        *(ulonglong2*)(op)     = make_ulonglong2(acc[i][0], acc[i][1]);
        *(ulonglong2*)(op + 4) = make_ulonglong2(acc[i][2], acc[i][3]);
        op += (size_t)HH * WW;
    }
}

extern "C" void kernel_launch(void* const* d_in, const int* in_sizes, int n_in,
                              void* d_out, int out_size) {
    const float* x    = (const float*)d_in[0];
    const float* w    = (const float*)d_in[1];
    const float* bias = (const float*)d_in[2];
    float* out        = (float*)d_out;

    repack_weights<<<(2 * ICH * 9 * 16 + 255) / 256, 256>>>(w);

    cudaFuncSetAttribute(conv3x3_kernel,
                         cudaFuncAttributeMaxDynamicSharedMemorySize, SMEM_BYTES);

    dim3 grid(WW / TW, HH / TH, 8 * 2);  // 16 x 32 x 16 = 8192 CTAs
    conv3x3_kernel<<<grid, 256, SMEM_BYTES>>>(x, bias, out);
}

// round 6
// speedup vs baseline: 1.9914x; 1.9914x over previous
#include <cuda_runtime.h>
#include <cuda_bf16.h>
#include <cstdint>

#define NIMG 8

// ---- global scratch (static __device__ arrays are the allowed scratch) ----
__device__ unsigned xth_g[NIMG * 512 * 512 * 16];   // [n][y][x][ic-pair] bf16x2 hi
__device__ unsigned xtl_g[NIMG * 512 * 512 * 16];   // lo
__device__ uint4    wfrag_g[1152];                  // [r][h][s][oc][ic] bf16 (18432)

// pack two floats to bf16x2: lower16 = f0, upper16 = f1
__device__ __forceinline__ unsigned pkbf(float f0, float f1) {
    unsigned u;
    asm("cvt.rn.bf16x2.f32 %0, %1, %2;" : "=r"(u) : "f"(f1), "f"(f0));
    return u;
}
__device__ __forceinline__ uint32_t smem_u32(const void* p) {
    uint32_t a;
    asm("{ .reg .u64 t; cvta.to.shared.u64 t, %1; cvt.u32.u64 %0, t; }" : "=r"(a) : "l"(p));
    return a;
}
__device__ __forceinline__ void ldsm4(unsigned* r, uint32_t a) {
    asm volatile("ldmatrix.sync.aligned.m8n8.x4.shared.b16 {%0,%1,%2,%3}, [%4];"
                 : "=r"(r[0]), "=r"(r[1]), "=r"(r[2]), "=r"(r[3]) : "r"(a));
}
__device__ __forceinline__ void mma_bf16(float* c, const unsigned* a, unsigned b0, unsigned b1) {
    asm volatile("mma.sync.aligned.m16n8k16.row.col.f32.bf16.bf16.f32 "
                 "{%0,%1,%2,%3}, {%4,%5,%6,%7}, {%8,%9}, {%0,%1,%2,%3};"
                 : "+f"(c[0]), "+f"(c[1]), "+f"(c[2]), "+f"(c[3])
                 : "r"(a[0]), "r"(a[1]), "r"(a[2]), "r"(a[3]), "r"(b0), "r"(b1));
}

// ---------------- prepass: weights -> [r][h][s][oc][ic] bf16 ----------------
__global__ void prep_weights(const float* __restrict__ w) {
    int idx = blockIdx.x * blockDim.x + threadIdx.x;
    if (idx >= 18432) return;
    int ic = idx & 31;
    int oc = (idx >> 5) & 31;
    int s  = (idx >> 10) % 3;
    int h  = (idx / 3072) & 1;
    int r  = idx / 6144;
    float f = w[(oc * 32 + ic) * 9 + r * 3 + s];
    __nv_bfloat16 hi = __float2bfloat16_rn(f);
    unsigned short bits = (h == 0)
        ? __bfloat16_as_ushort(hi)
        : __bfloat16_as_ushort(__float2bfloat16_rn(f - __bfloat162float(hi)));
    ((unsigned short*)wfrag_g)[idx] = bits;
}

// ---------------- prepass: x -> transposed hi/lo bf16 ----------------
__global__ void prep_split(const float* __restrict__ x) {
    extern __shared__ float xin[];     // [32][513]
    const int y = blockIdx.x, n = blockIdx.y, tid = threadIdx.x;
    for (int e = tid; e < 32 * 512; e += 256) {
        int ic = e >> 9, gx = e & 511;
        xin[ic * 513 + gx] = x[((size_t)(n * 32 + ic) * 512 + y) * 512 + gx];
    }
    __syncthreads();
    unsigned base = (unsigned)(n * 512 + y) * 8192u;
    for (int e = tid; e < 8192; e += 256) {
        int gx = e >> 4, p = e & 15, ic = p * 2;
        float f0 = xin[ic * 513 + gx];
        float f1 = xin[(ic + 1) * 513 + gx];
        unsigned hi = pkbf(f0, f1);
        float fh0 = __uint_as_float(hi << 16);
        float fh1 = __uint_as_float(hi & 0xffff0000u);
        unsigned lo = pkbf(f0 - fh0, f1 - fh1);
        xth_g[base + e] = hi;
        xtl_g[base + e] = lo;
    }
}

// ---------------- main: implicit GEMM via mma.sync ----------------
// smem: scr hi [258x80B] @0, scr lo @20800, wsm @41600 (576 rows x 80B), bias @87680
#define SM_SCRH 0
#define SM_SCRL 20800
#define SM_WSM  41600
#define SM_BIAS 87680
#define SM_TOT  87808

__global__ void __launch_bounds__(128, 2) conv_mma(
    const float* __restrict__ bias, float* __restrict__ out)
{
    extern __shared__ unsigned char sm[];
    const uint32_t sb = smem_u32(sm);
    const int tid = threadIdx.x, wid = tid >> 5, l = tid & 31;
    const int n = blockIdx.z, y = blockIdx.y, x0 = blockIdx.x * 256;

    // stage weight tiles (rows of 64B -> stride 80B) + bias
    for (int e = tid; e < 2304; e += 128) {
        int row = e >> 2, k = e & 3;
        *(uint4*)(sm + SM_WSM + row * 80 + k * 16) = wfrag_g[e];
    }
    if (tid < 32) ((float*)(sm + SM_BIAS))[tid] = bias[tid];

    float acc[4][4][4];
    #pragma unroll
    for (int a = 0; a < 4; a++)
        #pragma unroll
        for (int b = 0; b < 4; b++)
            #pragma unroll
            for (int c = 0; c < 4; c++) acc[a][b][c] = 0.f;

    // lane-constant fragments addressing
    const int      colA = l & 15;
    const uint32_t kA   = (l & 16) ? 16u : 0u;
    const int      ocB  = ((l & 16) >> 1) + (l & 7);
    const uint32_t kB   = (uint32_t)((l & 8) << 1);

    const uint4* xh4 = (const uint4*)xth_g;
    const uint4* xl4 = (const uint4*)xtl_g;

    for (int r = 0; r < 3; r++) {
        const int row = y + r - 1;
        if ((unsigned)row >= 512u) continue;          // uniform across CTA
        __syncthreads();                               // prior reads of scr done
        // ---- stage hi/lo row window [x0-1, x0+256] ----
        const size_t rb = (size_t)(n * 512 + row) * 512;
        for (int e = tid; e < 2064; e += 128) {
            int h  = (e >= 1032);
            int e2 = e - (h ? 1032 : 0);
            int col = e2 >> 2, k = e2 & 3;
            int gx = x0 - 1 + col;
            uint4 v = make_uint4(0, 0, 0, 0);
            if ((unsigned)gx < 512u) v = (h ? xl4 : xh4)[(rb + gx) * 4 + k];
            *(uint4*)(sm + (h ? SM_SCRL : SM_SCRH) + col * 80 + k * 16) = v;
        }
        __syncthreads();

        // ---- K loop: kh (ic halves) x s ----
        #pragma unroll
        for (int kh = 0; kh < 2; kh++) {
            #pragma unroll
            for (int s = 0; s < 3; s++) {
                unsigned Bh[8], Bl[8];
                uint32_t wbh = sb + SM_WSM + (uint32_t)(((r * 2 + 0) * 3 + s) * 2560) + kB + kh * 32;
                uint32_t wbl = sb + SM_WSM + (uint32_t)(((r * 2 + 1) * 3 + s) * 2560) + kB + kh * 32;
                ldsm4(Bh + 0, wbh + (uint32_t)(ocB * 80));
                ldsm4(Bh + 4, wbh + (uint32_t)((16 + ocB) * 80));
                ldsm4(Bl + 0, wbl + (uint32_t)(ocB * 80));
                ldsm4(Bl + 4, wbl + (uint32_t)((16 + ocB) * 80));
                #pragma unroll
                for (int mt = 0; mt < 4; mt++) {
                    unsigned Ah[4], Al[4];
                    uint32_t aoff = (uint32_t)((wid * 64 + mt * 16 + s + colA) * 80) + kA + kh * 32;
                    ldsm4(Ah, sb + SM_SCRH + aoff);
                    ldsm4(Al, sb + SM_SCRL + aoff);
                    #pragma unroll
                    for (int nt = 0; nt < 4; nt++) {
                        int bi = (nt >> 1) * 4 + (nt & 1) * 2;
                        mma_bf16(acc[mt][nt], Ah, Bh[bi], Bh[bi + 1]);   // xh*wh
                        mma_bf16(acc[mt][nt], Ah, Bl[bi], Bl[bi + 1]);   // xh*wl
                        mma_bf16(acc[mt][nt], Al, Bh[bi], Bh[bi + 1]);   // xl*wh
                    }
                }
            }
        }
    }

    // ---- epilogue: transpose through smem, coalesced store ----
    __syncthreads();
    float* accs = (float*)sm;          // [32 oc][260 px] stride 260 floats
    #pragma unroll
    for (int mt = 0; mt < 4; mt++)
        #pragma unroll
        for (int nt = 0; nt < 4; nt++) {
            int mb  = wid * 64 + mt * 16 + (l >> 2);
            int oc0 = nt * 8 + ((l & 3) * 2);
            accs[oc0 * 260 + mb]           = acc[mt][nt][0];
            accs[(oc0 + 1) * 260 + mb]     = acc[mt][nt][1];
            accs[oc0 * 260 + mb + 8]       = acc[mt][nt][2];
            accs[(oc0 + 1) * 260 + mb + 8] = acc[mt][nt][3];
        }
    __syncthreads();
    for (int e = tid; e < 2048; e += 128) {
        int oc = e >> 6, k = e & 63;
        float4 v = *(float4*)((unsigned char*)accs + oc * 1040 + k * 16);
        float b = ((float*)(sm + SM_BIAS))[oc];
        v.x += b; v.y += b; v.z += b; v.w += b;
        ((float4*)out)[((size_t)(n * 32 + oc) * 512 + y) * 128 + blockIdx.x * 64 + k] = v;
    }
}

extern "C" void kernel_launch(void* const* d_in, const int* in_sizes, int n_in,
                              void* d_out, int out_size) {
    const float* x    = (const float*)d_in[0];
    const float* w    = (const float*)d_in[1];
    const float* bias = (const float*)d_in[2];
    float* out        = (float*)d_out;

    prep_weights<<<72, 256>>>(w);

    cudaFuncSetAttribute(prep_split, cudaFuncAttributeMaxDynamicSharedMemorySize, 32 * 513 * 4);
    prep_split<<<dim3(512, NIMG), 256, 32 * 513 * 4>>>(x);

    cudaFuncSetAttribute(conv_mma, cudaFuncAttributeMaxDynamicSharedMemorySize, SM_TOT);
    conv_mma<<<dim3(2, 512, NIMG), 128, SM_TOT>>>(bias, out);
}

// round 7
// speedup vs baseline: 2.6597x; 1.3356x over previous
#include <cuda_runtime.h>
#include <cuda_bf16.h>
#include <cstdint>

#define NIMG 8

__device__ uint4 wfrag_g[1152];   // [r][h][s][oc][ic] bf16 (18432 halves)

// pack two floats to bf16x2: lower16 = f0, upper16 = f1
__device__ __forceinline__ unsigned pkbf(float f0, float f1) {
    unsigned u;
    asm("cvt.rn.bf16x2.f32 %0, %1, %2;" : "=r"(u) : "f"(f1), "f"(f0));
    return u;
}
__device__ __forceinline__ uint32_t smem_u32(const void* p) {
    uint32_t a;
    asm("{ .reg .u64 t; cvta.to.shared.u64 t, %1; cvt.u32.u64 %0, t; }" : "=r"(a) : "l"(p));
    return a;
}
__device__ __forceinline__ void ldsm4(unsigned* r, uint32_t a) {
    asm volatile("ldmatrix.sync.aligned.m8n8.x4.shared.b16 {%0,%1,%2,%3}, [%4];"
                 : "=r"(r[0]), "=r"(r[1]), "=r"(r[2]), "=r"(r[3]) : "r"(a));
}
__device__ __forceinline__ void mma_bf16(float* c, const unsigned* a, unsigned b0, unsigned b1) {
    asm volatile("mma.sync.aligned.m16n8k16.row.col.f32.bf16.bf16.f32 "
                 "{%0,%1,%2,%3}, {%4,%5,%6,%7}, {%8,%9}, {%0,%1,%2,%3};"
                 : "+f"(c[0]), "+f"(c[1]), "+f"(c[2]), "+f"(c[3])
                 : "r"(a[0]), "r"(a[1]), "r"(a[2]), "r"(a[3]), "r"(b0), "r"(b1));
}

// ---------------- prepass: weights -> [r][h][s][oc][ic] bf16 ----------------
__global__ void prep_weights(const float* __restrict__ w) {
    int idx = blockIdx.x * blockDim.x + threadIdx.x;
    if (idx >= 18432) return;
    int ic = idx & 31;
    int oc = (idx >> 5) & 31;
    int s  = (idx >> 10) % 3;
    int h  = (idx / 3072) & 1;
    int r  = idx / 6144;
    float f = w[(oc * 32 + ic) * 9 + r * 3 + s];
    __nv_bfloat16 hi = __float2bfloat16_rn(f);
    unsigned short bits = (h == 0)
        ? __bfloat16_as_ushort(hi)
        : __bfloat16_as_ushort(__float2bfloat16_rn(f - __bfloat162float(hi)));
    ((unsigned short*)wfrag_g)[idx] = bits;
}

// ---------------- main: fused split + implicit GEMM via mma.sync ----------------
// smem: scr hi [258 x 80B] @0, scr lo @20800, wsm @41600 (576 rows x 80B), bias @87680
#define SM_SCRH 0
#define SM_SCRL 20800
#define SM_WSM  41600
#define SM_BIAS 87680
#define SM_TOT  87808

__global__ void __launch_bounds__(128, 2) conv_mma(
    const float* __restrict__ x, const float* __restrict__ bias, float* __restrict__ out)
{
    extern __shared__ unsigned char sm[];
    const uint32_t sb = smem_u32(sm);
    const int tid = threadIdx.x, wid = tid >> 5, l = tid & 31;
    const int n = blockIdx.z, y = blockIdx.y, x0 = blockIdx.x * 256;

    // stage weight tiles (rows of 64B -> stride 80B) + bias
    for (int e = tid; e < 2304; e += 128) {
        int row = e >> 2, k = e & 3;
        *(uint4*)(sm + SM_WSM + row * 80 + k * 16) = wfrag_g[e];
    }
    if (tid < 32) ((float*)(sm + SM_BIAS))[tid] = bias[tid];

    float acc[4][4][4];
    #pragma unroll
    for (int a = 0; a < 4; a++)
        #pragma unroll
        for (int b = 0; b < 4; b++)
            #pragma unroll
            for (int c = 0; c < 4; c++) acc[a][b][c] = 0.f;

    // lane-constant fragment addressing
    const int      colA = l & 15;
    const uint32_t kA   = (l & 16) ? 16u : 0u;
    const int      ocB  = ((l & 16) >> 1) + (l & 7);
    const uint32_t kB   = (uint32_t)((l & 8) << 1);

    for (int r = 0; r < 3; r++) {
        const int row = y + r - 1;
        if ((unsigned)row >= 512u) continue;           // zero-pad row: no contribution
        __syncthreads();                                // prior reads of scr done

        // ---- fused staging: split x fp32 -> hi/lo bf16x2, transposed [col][icpair] ----
        {
            const float* xrow = x + ((size_t)n * 32 * 512 + row) * 512;
            for (int c = tid; c < 258; c += 128) {
                int gx = x0 - 1 + c;
                const bool valid = (unsigned)gx < 512u;
                const float* xp = xrow + gx;
                unsigned hb[4], lb[4];
                #pragma unroll
                for (int pq = 0; pq < 4; pq++) {
                    #pragma unroll
                    for (int j = 0; j < 4; j++) {
                        int p = pq * 4 + j;
                        float f0 = 0.f, f1 = 0.f;
                        if (valid) {
                            f0 = xp[(size_t)(2 * p)     * 262144];
                            f1 = xp[(size_t)(2 * p + 1) * 262144];
                        }
                        unsigned hi = pkbf(f0, f1);
                        float fh0 = __uint_as_float(hi << 16);
                        float fh1 = __uint_as_float(hi & 0xffff0000u);
                        hb[j] = hi;
                        lb[j] = pkbf(f0 - fh0, f1 - fh1);
                    }
                    *(uint4*)(sm + SM_SCRH + c * 80 + pq * 16) = make_uint4(hb[0], hb[1], hb[2], hb[3]);
                    *(uint4*)(sm + SM_SCRL + c * 80 + pq * 16) = make_uint4(lb[0], lb[1], lb[2], lb[3]);
                }
            }
        }
        __syncthreads();

        // ---- K loop: kh (ic halves) x s ----
        #pragma unroll
        for (int kh = 0; kh < 2; kh++) {
            #pragma unroll
            for (int s = 0; s < 3; s++) {
                unsigned Bh[8], Bl[8];
                uint32_t wbh = sb + SM_WSM + (uint32_t)(((r * 2 + 0) * 3 + s) * 2560) + kB + kh * 32;
                uint32_t wbl = sb + SM_WSM + (uint32_t)(((r * 2 + 1) * 3 + s) * 2560) + kB + kh * 32;
                ldsm4(Bh + 0, wbh + (uint32_t)(ocB * 80));
                ldsm4(Bh + 4, wbh + (uint32_t)((16 + ocB) * 80));
                ldsm4(Bl + 0, wbl + (uint32_t)(ocB * 80));
                ldsm4(Bl + 4, wbl + (uint32_t)((16 + ocB) * 80));
                #pragma unroll
                for (int mt = 0; mt < 4; mt++) {
                    unsigned Ah[4], Al[4];
                    uint32_t aoff = (uint32_t)((wid * 64 + mt * 16 + s + colA) * 80) + kA + kh * 32;
                    ldsm4(Ah, sb + SM_SCRH + aoff);
                    ldsm4(Al, sb + SM_SCRL + aoff);
                    #pragma unroll
                    for (int nt = 0; nt < 4; nt++) {
                        int bi = (nt >> 1) * 4 + (nt & 1) * 2;
                        mma_bf16(acc[mt][nt], Ah, Bh[bi], Bh[bi + 1]);   // xh*wh
                        mma_bf16(acc[mt][nt], Ah, Bl[bi], Bl[bi + 1]);   // xh*wl
                        mma_bf16(acc[mt][nt], Al, Bh[bi], Bh[bi + 1]);   // xl*wh
                    }
                }
            }
        }
    }

    // ---- epilogue: transpose through smem, coalesced store ----
    __syncthreads();
    float* accs = (float*)sm;          // [32 oc][260 px] stride 260 floats
    #pragma unroll
    for (int mt = 0; mt < 4; mt++)
        #pragma unroll
        for (int nt = 0; nt < 4; nt++) {
            int mb  = wid * 64 + mt * 16 + (l >> 2);
            int oc0 = nt * 8 + ((l & 3) * 2);
            accs[oc0 * 260 + mb]           = acc[mt][nt][0];
            accs[(oc0 + 1) * 260 + mb]     = acc[mt][nt][1];
            accs[oc0 * 260 + mb + 8]       = acc[mt][nt][2];
            accs[(oc0 + 1) * 260 + mb + 8] = acc[mt][nt][3];
        }
    __syncthreads();
    for (int e = tid; e < 2048; e += 128) {
        int oc = e >> 6, k = e & 63;
        float4 v = *(float4*)((unsigned char*)accs + oc * 1040 + k * 16);
        float b = ((float*)(sm + SM_BIAS))[oc];
        v.x += b; v.y += b; v.z += b; v.w += b;
        ((float4*)out)[((size_t)(n * 32 + oc) * 512 + y) * 128 + blockIdx.x * 64 + k] = v;
    }
}

extern "C" void kernel_launch(void* const* d_in, const int* in_sizes, int n_in,
                              void* d_out, int out_size) {
    const float* x    = (const float*)d_in[0];
    const float* w    = (const float*)d_in[1];
    const float* bias = (const float*)d_in[2];
    float* out        = (float*)d_out;

    prep_weights<<<72, 256>>>(w);

    cudaFuncSetAttribute(conv_mma, cudaFuncAttributeMaxDynamicSharedMemorySize, SM_TOT);
    conv_mma<<<dim3(2, 512, NIMG), 128, SM_TOT>>>(x, bias, out);
}

// round 14
// speedup vs baseline: 3.0343x; 1.1409x over previous
#include <cuda_runtime.h>
#include <cuda_bf16.h>
#include <cstdint>

#define NIMG 8

__device__ uint4 wfrag_g[1152];   // [r][h][s][oc][ic] bf16 (18432 halves)

__device__ __forceinline__ unsigned pkbf(float f0, float f1) {
    unsigned u;
    asm("cvt.rn.bf16x2.f32 %0, %1, %2;" : "=r"(u) : "f"(f1), "f"(f0));
    return u;
}
__device__ __forceinline__ uint32_t smem_u32(const void* p) {
    uint32_t a;
    asm("{ .reg .u64 t; cvta.to.shared.u64 t, %1; cvt.u32.u64 %0, t; }" : "=r"(a) : "l"(p));
    return a;
}
__device__ __forceinline__ void ldsm4(unsigned* r, uint32_t a) {
    asm volatile("ldmatrix.sync.aligned.m8n8.x4.shared.b16 {%0,%1,%2,%3}, [%4];"
                 : "=r"(r[0]), "=r"(r[1]), "=r"(r[2]), "=r"(r[3]) : "r"(a));
}
__device__ __forceinline__ void mma_bf16(float* c, const unsigned* a, unsigned b0, unsigned b1) {
    asm volatile("mma.sync.aligned.m16n8k16.row.col.f32.bf16.bf16.f32 "
                 "{%0,%1,%2,%3}, {%4,%5,%6,%7}, {%8,%9}, {%0,%1,%2,%3};"
                 : "+f"(c[0]), "+f"(c[1]), "+f"(c[2]), "+f"(c[3])
                 : "r"(a[0]), "r"(a[1]), "r"(a[2]), "r"(a[3]), "r"(b0), "r"(b1));
}

// ---------------- prepass: weights -> [r][h][s][oc][ic] bf16 ----------------
__global__ void prep_weights(const float* __restrict__ w) {
    int idx = blockIdx.x * blockDim.x + threadIdx.x;
    if (idx >= 18432) return;
    int ic = idx & 31;
    int oc = (idx >> 5) & 31;
    int s  = (idx >> 10) % 3;
    int h  = (idx / 3072) & 1;
    int r  = idx / 6144;
    float f = w[(oc * 32 + ic) * 9 + r * 3 + s];
    __nv_bfloat16 hi = __float2bfloat16_rn(f);
    unsigned short bits = (h == 0)
        ? __bfloat16_as_ushort(hi)
        : __bfloat16_as_ushort(__float2bfloat16_rn(f - __bfloat162float(hi)));
    ((unsigned short*)wfrag_g)[idx] = bits;
}

// ---------------- main: pipelined fused split + implicit GEMM ----------------
// scr: 260 rows x 80B, hi @0, lo @20800; weights @41600 (576 x 80B); bias @87680
#define SSTR    80
#define SM_SCRH 0
#define SM_SCRL 20800
#define SM_WSM  41600
#define SM_BIAS 87680
#define SM_TOT  87808

__global__ void __launch_bounds__(128, 2) conv_mma(
    const float* __restrict__ x, const float* __restrict__ bias, float* __restrict__ out)
{
    extern __shared__ unsigned char sm[];
    const uint32_t sb = smem_u32(sm);
    const int tid = threadIdx.x, wid = tid >> 5, l = tid & 31;
    const int n = blockIdx.z, y = blockIdx.y, x0 = blockIdx.x * 256;

    // stage weight tiles (rows of 64B -> stride 80B) + bias
    for (int e = tid; e < 2304; e += 128) {
        int row = e >> 2, k = e & 3;
        *(uint4*)(sm + SM_WSM + row * 80 + k * 16) = wfrag_g[e];
    }
    if (tid < 32) ((float*)(sm + SM_BIAS))[tid] = bias[tid];

    float acc[4][4][4];
    #pragma unroll
    for (int a = 0; a < 4; a++)
        #pragma unroll
        for (int b = 0; b < 4; b++)
            #pragma unroll
            for (int c = 0; c < 4; c++) acc[a][b][c] = 0.f;

    // lane-constant fragment addressing
    const int      colA = l & 15;
    const uint32_t kA   = (l & 16) ? 16u : 0u;
    const int      ocB  = ((l & 16) >> 1) + (l & 7);
    const uint32_t kB   = (uint32_t)((l & 8) << 1);

    const float* xbase = x + (size_t)n * 32 * 512 * 512;
    const int gxa = x0 - 2 + tid;              // cols tid and tid+128
    const int gxb = gxa + 128;
    const int ic2 = tid & 31, c4 = tid >> 5;   // leftover: cols 256..259
    const int gx2 = x0 + 254 + c4;

    float pa[32], pb[32], lf;

    auto prefetch = [&](int r) {
        const int row = y + r - 1;
        const bool vr = (unsigned)row < 512u;
        const float* xrow = xbase + (size_t)row * 512;
        const bool va = vr && ((unsigned)gxa < 512u);
        const bool vb = vr && ((unsigned)gxb < 512u);
        #pragma unroll
        for (int ic = 0; ic < 32; ic++) {
            pa[ic] = va ? xrow[(size_t)ic * 262144 + gxa] : 0.f;
            pb[ic] = vb ? xrow[(size_t)ic * 262144 + gxb] : 0.f;
        }
        lf = (vr && (unsigned)gx2 < 512u) ? xrow[(size_t)ic2 * 262144 + gx2] : 0.f;
    };

    prefetch(0);

    for (int r = 0; r < 3; r++) {
        // ---- flush prefetched row: split -> hi/lo bf16x2, transposed ----
        #pragma unroll
        for (int half = 0; half < 2; half++) {
            const float* pf = half ? pb : pa;
            const int col = tid + half * 128;
            #pragma unroll
            for (int pq = 0; pq < 4; pq++) {
                unsigned hb[4], lb[4];
                #pragma unroll
                for (int j = 0; j < 4; j++) {
                    const int p = pq * 4 + j;
                    float f0 = pf[2 * p];
                    float f1 = pf[2 * p + 1];
                    unsigned hi = pkbf(f0, f1);
                    float fh0 = __uint_as_float(hi << 16);
                    float fh1 = __uint_as_float(hi & 0xffff0000u);
                    hb[j] = hi;
                    lb[j] = pkbf(f0 - fh0, f1 - fh1);
                }
                *(uint4*)(sm + SM_SCRH + col * SSTR + pq * 16) = make_uint4(hb[0], hb[1], hb[2], hb[3]);
                *(uint4*)(sm + SM_SCRL + col * SSTR + pq * 16) = make_uint4(lb[0], lb[1], lb[2], lb[3]);
            }
        }
        {   // leftover cols 256..259 (one float per thread)
            const uint32_t off = (uint32_t)(256 + c4) * SSTR
                               + (uint32_t)(ic2 >> 3) * 16
                               + (uint32_t)((ic2 >> 1) & 3) * 4
                               + (uint32_t)(ic2 & 1) * 2;
            __nv_bfloat16 hi = __float2bfloat16_rn(lf);
            *(unsigned short*)(sm + SM_SCRH + off) = __bfloat16_as_ushort(hi);
            *(unsigned short*)(sm + SM_SCRL + off) =
                __bfloat16_as_ushort(__float2bfloat16_rn(lf - __bfloat162float(hi)));
        }
        __syncthreads();

        if (r < 2) prefetch(r + 1);            // LDGs fly under the MMA phase

        // ---- K loop: kh (ic halves) x s ----
        #pragma unroll
        for (int kh = 0; kh < 2; kh++) {
            #pragma unroll
            for (int s = 0; s < 3; s++) {
                unsigned Bh[8], Bl[8];
                uint32_t wbh = sb + SM_WSM + (uint32_t)(((r * 2 + 0) * 3 + s) * 2560) + kB + kh * 32;
                uint32_t wbl = sb + SM_WSM + (uint32_t)(((r * 2 + 1) * 3 + s) * 2560) + kB + kh * 32;
                ldsm4(Bh + 0, wbh + (uint32_t)(ocB * 80));
                ldsm4(Bh + 4, wbh + (uint32_t)((16 + ocB) * 80));
                ldsm4(Bl + 0, wbl + (uint32_t)(ocB * 80));
                ldsm4(Bl + 4, wbl + (uint32_t)((16 + ocB) * 80));
                #pragma unroll
                for (int mt = 0; mt < 4; mt++) {
                    unsigned Ah[4], Al[4];
                    uint32_t aoff = (uint32_t)((wid * 64 + mt * 16 + s + 1 + colA) * SSTR) + kA + kh * 32;
                    ldsm4(Ah, sb + SM_SCRH + aoff);
                    ldsm4(Al, sb + SM_SCRL + aoff);
                    #pragma unroll
                    for (int nt = 0; nt < 4; nt++) {
                        int bi = (nt >> 1) * 4 + (nt & 1) * 2;
                        mma_bf16(acc[mt][nt], Ah, Bh[bi], Bh[bi + 1]);   // xh*wh
                        mma_bf16(acc[mt][nt], Ah, Bl[bi], Bl[bi + 1]);   // xh*wl
                        mma_bf16(acc[mt][nt], Al, Bh[bi], Bh[bi + 1]);   // xl*wh
                    }
                }
            }
        }
        __syncthreads();
    }

    // ---- epilogue: transpose through smem, coalesced store ----
    float* accs = (float*)sm;          // [32 oc][260 px]
    #pragma unroll
    for (int mt = 0; mt < 4; mt++)
        #pragma unroll
        for (int nt = 0; nt < 4; nt++) {
            int mb  = wid * 64 + mt * 16 + (l >> 2);
            int oc0 = nt * 8 + ((l & 3) * 2);
            accs[oc0 * 260 + mb]           = acc[mt][nt][0];
            accs[(oc0 + 1) * 260 + mb]     = acc[mt][nt][1];
            accs[oc0 * 260 + mb + 8]       = acc[mt][nt][2];
            accs[(oc0 + 1) * 260 + mb + 8] = acc[mt][nt][3];
        }
    __syncthreads();
    for (int e = tid; e < 2048; e += 128) {
        int oc = e >> 6, k = e & 63;
        float4 v = *(float4*)((unsigned char*)accs + oc * 1040 + k * 16);
        float b = ((float*)(sm + SM_BIAS))[oc];
        v.x += b; v.y += b; v.z += b; v.w += b;
        ((float4*)out)[((size_t)(n * 32 + oc) * 512 + y) * 128 + blockIdx.x * 64 + k] = v;
    }
}

extern "C" void kernel_launch(void* const* d_in, const int* in_sizes, int n_in,
                              void* d_out, int out_size) {
    const float* x    = (const float*)d_in[0];
    const float* w    = (const float*)d_in[1];
    const float* bias = (const float*)d_in[2];
    float* out        = (float*)d_out;

    prep_weights<<<72, 256>>>(w);

    cudaFuncSetAttribute(conv_mma, cudaFuncAttributeMaxDynamicSharedMemorySize, SM_TOT);
    conv_mma<<<dim3(2, 512, NIMG), 128, SM_TOT>>>(x, bias, out);
}

// round 15
// speedup vs baseline: 3.6643x; 1.2077x over previous
#include <cuda_runtime.h>
#include <cuda_bf16.h>
#include <cstdint>

#define NIMG 8
#define STRIP 16

__device__ uint4 wfrag_g[1152];   // [r][h][s][oc][ic] bf16 (18432 halves)

__device__ __forceinline__ unsigned pkbf(float f0, float f1) {
    unsigned u;
    asm("cvt.rn.bf16x2.f32 %0, %1, %2;" : "=r"(u) : "f"(f1), "f"(f0));
    return u;
}
__device__ __forceinline__ uint32_t smem_u32(const void* p) {
    uint32_t a;
    asm("{ .reg .u64 t; cvta.to.shared.u64 t, %1; cvt.u32.u64 %0, t; }" : "=r"(a) : "l"(p));
    return a;
}
__device__ __forceinline__ void ldsm4(unsigned* r, uint32_t a) {
    asm volatile("ldmatrix.sync.aligned.m8n8.x4.shared.b16 {%0,%1,%2,%3}, [%4];"
                 : "=r"(r[0]), "=r"(r[1]), "=r"(r[2]), "=r"(r[3]) : "r"(a));
}
__device__ __forceinline__ void mma_bf16(float* c, const unsigned* a, unsigned b0, unsigned b1) {
    asm volatile("mma.sync.aligned.m16n8k16.row.col.f32.bf16.bf16.f32 "
                 "{%0,%1,%2,%3}, {%4,%5,%6,%7}, {%8,%9}, {%0,%1,%2,%3};"
                 : "+f"(c[0]), "+f"(c[1]), "+f"(c[2]), "+f"(c[3])
                 : "r"(a[0]), "r"(a[1]), "r"(a[2]), "r"(a[3]), "r"(b0), "r"(b1));
}

// ---------------- prepass: weights -> [r][h][s][oc][ic] bf16 ----------------
__global__ void prep_weights(const float* __restrict__ w) {
    int idx = blockIdx.x * blockDim.x + threadIdx.x;
    if (idx >= 18432) return;
    int ic = idx & 31;
    int oc = (idx >> 5) & 31;
    int s  = (idx >> 10) % 3;
    int h  = (idx / 3072) & 1;
    int r  = idx / 6144;
    float f = w[(oc * 32 + ic) * 9 + r * 3 + s];
    __nv_bfloat16 hi = __float2bfloat16_rn(f);
    unsigned short bits = (h == 0)
        ? __bfloat16_as_ushort(hi)
        : __bfloat16_as_ushort(__float2bfloat16_rn(f - __bfloat162float(hi)));
    ((unsigned short*)wfrag_g)[idx] = bits;
}

// ---------------- main: rolling-row strip, ring-buffered implicit GEMM ----------------
// scr: 3 ring slots x 132 rows x 80B per plane; hi @0, lo @31680
// weights @63360 (576 x 80B); bias @109440
#define SSTR    80
#define SLOT    10560
#define SM_SCRH 0
#define SM_SCRL 31680
#define SM_WSM  63360
#define SM_BIAS 109440
#define SM_TOT  109568

__global__ void __launch_bounds__(128, 2) conv_mma(
    const float* __restrict__ x, const float* __restrict__ bias, float* __restrict__ out)
{
    extern __shared__ unsigned char sm[];
    const uint32_t sb = smem_u32(sm);
    const int tid = threadIdx.x, wid = tid >> 5, l = tid & 31;
    const int n = blockIdx.z, y0 = blockIdx.y * STRIP, x0 = blockIdx.x * 128;

    // stage weight tiles (rows of 64B -> stride 80B) + bias
    for (int e = tid; e < 2304; e += 128) {
        int row = e >> 2, k = e & 3;
        *(uint4*)(sm + SM_WSM + row * 80 + k * 16) = wfrag_g[e];
    }
    if (tid < 32) ((float*)(sm + SM_BIAS))[tid] = bias[tid];

    // lane-constant fragment addressing
    const int      colA = l & 15;
    const uint32_t kA   = (l & 16) ? 16u : 0u;
    const int      ocB  = ((l & 16) >> 1) + (l & 7);
    const uint32_t kB   = (uint32_t)((l & 8) << 1);

    const float* xbase = x + (size_t)n * 32 * 512 * 512;
    const int gxa = x0 - 2 + tid;              // window col tid
    const int ic2 = tid & 31, c4 = tid >> 5;   // leftover: cols 128..131
    const int gx2 = x0 + 126 + c4;

    float pa[32], lf;

    auto prefetch = [&](int row) {
        const bool vr = (unsigned)row < 512u;
        const float* xrow = xbase + (size_t)row * 512;
        const bool va = vr && ((unsigned)gxa < 512u);
        #pragma unroll
        for (int ic = 0; ic < 32; ic++)
            pa[ic] = va ? xrow[(size_t)ic * 262144 + gxa] : 0.f;
        lf = (vr && (unsigned)gx2 < 512u) ? xrow[(size_t)ic2 * 262144 + gx2] : 0.f;
    };

    auto flush = [&](int slot) {
        const uint32_t base = (uint32_t)slot * SLOT + (uint32_t)tid * SSTR;
        #pragma unroll
        for (int pq = 0; pq < 4; pq++) {
            unsigned hb[4], lb[4];
            #pragma unroll
            for (int j = 0; j < 4; j++) {
                const int p = pq * 4 + j;
                float f0 = pa[2 * p], f1 = pa[2 * p + 1];
                unsigned hi = pkbf(f0, f1);
                float fh0 = __uint_as_float(hi << 16);
                float fh1 = __uint_as_float(hi & 0xffff0000u);
                hb[j] = hi;
                lb[j] = pkbf(f0 - fh0, f1 - fh1);
            }
            *(uint4*)(sm + SM_SCRH + base + pq * 16) = make_uint4(hb[0], hb[1], hb[2], hb[3]);
            *(uint4*)(sm + SM_SCRL + base + pq * 16) = make_uint4(lb[0], lb[1], lb[2], lb[3]);
        }
        const uint32_t off = (uint32_t)slot * SLOT + (uint32_t)(128 + c4) * SSTR
                           + (uint32_t)(ic2 >> 1) * 4 + (uint32_t)(ic2 & 1) * 2;
        __nv_bfloat16 hi = __float2bfloat16_rn(lf);
        *(unsigned short*)(sm + SM_SCRH + off) = __bfloat16_as_ushort(hi);
        *(unsigned short*)(sm + SM_SCRL + off) =
            __bfloat16_as_ushort(__float2bfloat16_rn(lf - __bfloat162float(hi)));
    };

    // ---- prologue: stage rows y0-1, y0, y0+1 ----
    #pragma unroll
    for (int st = 0; st < 3; st++) {
        const int rr = y0 - 1 + st;
        prefetch(rr);
        flush((rr + 3) % 3);
    }
    __syncthreads();
    prefetch(y0 + 2);

    for (int y = y0; y < y0 + STRIP; y++) {
        float acc[2][4][4];
        #pragma unroll
        for (int a = 0; a < 2; a++)
            #pragma unroll
            for (int b = 0; b < 4; b++)
                #pragma unroll
                for (int c = 0; c < 4; c++) acc[a][b][c] = 0.f;

        #pragma unroll
        for (int r = 0; r < 3; r++) {
            const int slot = (y + r - 1 + 3) % 3;
            const uint32_t hbase = sb + SM_SCRH + (uint32_t)slot * SLOT;
            const uint32_t lbase = sb + SM_SCRL + (uint32_t)slot * SLOT;
            #pragma unroll
            for (int kh = 0; kh < 2; kh++) {
                #pragma unroll
                for (int s = 0; s < 3; s++) {
                    unsigned Bh[8], Bl[8];
                    uint32_t wbh = sb + SM_WSM + (uint32_t)(((r * 2 + 0) * 3 + s) * 2560) + kB + kh * 32;
                    uint32_t wbl = sb + SM_WSM + (uint32_t)(((r * 2 + 1) * 3 + s) * 2560) + kB + kh * 32;
                    ldsm4(Bh + 0, wbh + (uint32_t)(ocB * 80));
                    ldsm4(Bh + 4, wbh + (uint32_t)((16 + ocB) * 80));
                    ldsm4(Bl + 0, wbl + (uint32_t)(ocB * 80));
                    ldsm4(Bl + 4, wbl + (uint32_t)((16 + ocB) * 80));
                    #pragma unroll
                    for (int mt = 0; mt < 2; mt++) {
                        unsigned Ah[4], Al[4];
                        uint32_t aoff = (uint32_t)((wid * 32 + mt * 16 + s + 1 + colA) * SSTR) + kA + kh * 32;
                        ldsm4(Ah, hbase + aoff);
                        ldsm4(Al, lbase + aoff);
                        #pragma unroll
                        for (int nt = 0; nt < 4; nt++) {
                            int bi = (nt >> 1) * 4 + (nt & 1) * 2;
                            mma_bf16(acc[mt][nt], Ah, Bh[bi], Bh[bi + 1]);   // xh*wh
                            mma_bf16(acc[mt][nt], Ah, Bl[bi], Bl[bi + 1]);   // xh*wl
                            mma_bf16(acc[mt][nt], Al, Bh[bi], Bh[bi + 1]);   // xl*wh
                        }
                    }
                }
            }
        }

        // ---- epilogue: direct STG (each warp-STG covers 8 full 32B sectors) ----
        #pragma unroll
        for (int mt = 0; mt < 2; mt++) {
            const int px0 = wid * 32 + mt * 16 + (l >> 2);
            #pragma unroll
            for (int nt = 0; nt < 4; nt++) {
                const int oc0 = nt * 8 + (l & 3) * 2;
                const float b0 = ((float*)(sm + SM_BIAS))[oc0];
                const float b1 = ((float*)(sm + SM_BIAS))[oc0 + 1];
                float* po = out + (((size_t)(n * 32 + oc0) * 512 + y)) * 512 + x0 + px0;
                po[0]          = acc[mt][nt][0] + b0;
                po[262144]     = acc[mt][nt][1] + b1;
                po[8]          = acc[mt][nt][2] + b0;
                po[262144 + 8] = acc[mt][nt][3] + b1;
            }
        }

        __syncthreads();                 // readers done with slot (y+2)%3 (old row y-1)
        flush((y + 2) % 3);              // row y+2 from prefetch regs
        prefetch(y + 3);                 // LDGs fly under next row's MMA phase
        __syncthreads();
    }
}

extern "C" void kernel_launch(void* const* d_in, const int* in_sizes, int n_in,
                              void* d_out, int out_size) {
    const float* x    = (const float*)d_in[0];
    const float* w    = (const float*)d_in[1];
    const float* bias = (const float*)d_in[2];
    float* out        = (float*)d_out;

    prep_weights<<<72, 256>>>(w);

    cudaFuncSetAttribute(conv_mma, cudaFuncAttributeMaxDynamicSharedMemorySize, SM_TOT);
    conv_mma<<<dim3(4, 512 / STRIP, NIMG), 128, SM_TOT>>>(x, bias, out);
}